// round 1
// baseline (speedup 1.0000x reference)
#include <cuda_runtime.h>

// Two 8-vectors computed by kernel A: [0..7] = q for batch row B-1 ("last"),
// [8..15] = q for all other rows ("common").
__device__ __align__(16) float g_q[16];

__device__ __forceinline__ float relu(float x) { return fmaxf(x, 0.0f); }

__constant__ int c_P0[8] = {0, 0, 4, 1, 2, 2, 6, 3};
__constant__ int c_P1[8] = {4, 1, 5, 5, 6, 3, 7, 7};

__global__ void __launch_bounds__(256, 1)
frap_compute_kernel(
    const float* __restrict__ state, int B,
    const float* __restrict__ dv_w1, const float* __restrict__ dv_b1,
    const float* __restrict__ dv_w2, const float* __restrict__ dv_b2,
    const float* __restrict__ dp_w1, const float* __restrict__ dp_b1,
    const float* __restrict__ dp_w2, const float* __restrict__ dp_b2,
    const float* __restrict__ emb_w, const float* __restrict__ emb_b,
    const float* __restrict__ cp_w1, const float* __restrict__ cp_b1,
    const float* __restrict__ cp_w2, const float* __restrict__ cp_b2,
    const float* __restrict__ cm_w1, const float* __restrict__ cm_b1,
    const float* __restrict__ cm_w2, const float* __restrict__ cm_b2,
    const float* __restrict__ cm_w3, const float* __restrict__ cm_b3,
    const float* __restrict__ cc_w1, const float* __restrict__ cc_b1,
    const float* __restrict__ cc_w2, const float* __restrict__ cc_b2,
    const float* __restrict__ q_w1,  const float* __restrict__ q_b1,
    const float* __restrict__ q_w2,  const float* __restrict__ q_b2,
    const float* __restrict__ q_w3,  const float* __restrict__ q_b3,
    const float* __restrict__ mask)
{
    __shared__ float s_cat[8][8];     // per-phase concat(x_phase, x_vehicle)
    __shared__ float s_d[8][16];      // embedding output
    __shared__ float s_pd[8][16];     // phase-pair demand
    __shared__ float s_z[32][56];     // z_last reshaped to (C=32, HW=56)
    __shared__ float s_y1[20][56];    // cm chain intermediate
    __shared__ float s_y2[20][56];    // y (mask features)
    __shared__ float s_z0[20][56];    // cp conv1 out (last path)
    __shared__ float s_z1[20][56];    // cp conv2 out (last path)
    __shared__ float s_z1c[20];       // cp chain out (common/zero path, pos-invariant)
    __shared__ float s_rc1[2][8][56]; // cc conv1, both paths
    __shared__ float s_rc2[2][56];    // cc conv2, both paths
    __shared__ float s_rsum[2][8];    // sum over h
    __shared__ float s_h1[2][16];
    __shared__ float s_h2[2][16];

    const int t = threadIdx.x;

    // ---- 1. Per-phase demand MLPs on state[B-1] -> cat (8 phases x 8 feats) ----
    if (t < 8) {
        const int p = t;
        const float sv = state[(size_t)(B - 1) * 16 + p];       // s[:8] -> dv_* ("x_phase")
        const float sp = state[(size_t)(B - 1) * 16 + 8 + p];   // s[8:16] -> dp_* ("x_vehicle")
        float h0 = relu(sv * dv_w1[p * 2 + 0] + dv_b1[p * 2 + 0]);
        float h1 = relu(sv * dv_w1[p * 2 + 1] + dv_b1[p * 2 + 1]);
        #pragma unroll
        for (int o = 0; o < 4; o++)
            s_cat[p][o] = relu(h0 * dv_w2[p * 8 + o * 2 + 0] +
                               h1 * dv_w2[p * 8 + o * 2 + 1] + dv_b2[p * 4 + o]);
        h0 = relu(sp * dp_w1[p * 2 + 0] + dp_b1[p * 2 + 0]);
        h1 = relu(sp * dp_w1[p * 2 + 1] + dp_b1[p * 2 + 1]);
        #pragma unroll
        for (int o = 0; o < 4; o++)
            s_cat[p][4 + o] = relu(h0 * dp_w2[p * 8 + o * 2 + 0] +
                                   h1 * dp_w2[p * 8 + o * 2 + 1] + dp_b2[p * 4 + o]);
    }
    __syncthreads();

    // ---- 2. Embedding: d[p][k] = relu(cat[p] . emb_w[k,:] + emb_b[k]) ----
    if (t < 128) {
        const int p = t >> 4, k = t & 15;
        float acc = emb_b[k];
        #pragma unroll
        for (int j = 0; j < 8; j++) acc += s_cat[p][j] * emb_w[k * 8 + j];
        s_d[p][k] = relu(acc);
    }
    __syncthreads();

    // ---- 3. Phase-pair demand ----
    if (t < 128) {
        const int q = t >> 4, k = t & 15;
        s_pd[q][k] = s_d[c_P0[q]][k] + s_d[c_P1[q]][k];
    }
    __syncthreads();

    // ---- 4. Build z (reshape of the (7,8,32) scatter into (32,7,8)) ----
    // flat index idx in [0,1792): reshaped view (c, pos) = (idx/56, idx%56);
    // original view (r, col, k) = (idx/256, (idx>>5)&7, idx&31).
    for (int idx = t; idx < 1792; idx += 256) {
        const int c = idx / 56, pos = idx % 56;
        const int r = idx >> 8, col = (idx >> 5) & 7, k = idx & 31;
        const int j = col;
        const int i = (r < j) ? r : r + 1;
        s_z[c][pos] = (k < 16) ? s_pd[i][k] : s_pd[j][k - 16];
    }

    // ---- 5. Mask chain: y0(4) -> y1(20) -> y2(20), per pos ----
    for (int idx = t; idx < 20 * 56; idx += 256) {
        const int o = idx / 56, pos = idx % 56;
        const float m = mask[pos];
        float acc = cm_b2[o];
        #pragma unroll
        for (int c = 0; c < 4; c++)
            acc += cm_w2[o * 4 + c] * relu(cm_w1[c] * m + cm_b1[c]);
        s_y1[o][pos] = relu(acc);
    }
    __syncthreads();
    for (int idx = t; idx < 20 * 56; idx += 256) {
        const int o = idx / 56, pos = idx % 56;
        float acc = cm_b3[o];
        #pragma unroll
        for (int c = 0; c < 20; c++) acc += cm_w3[o * 20 + c] * s_y1[c][pos];
        s_y2[o][pos] = relu(acc);
    }
    __syncthreads();  // also covers s_z writes from step 4

    // ---- 6. cp conv chain (last path) ----
    for (int idx = t; idx < 20 * 56; idx += 256) {
        const int o = idx / 56, pos = idx % 56;
        float acc = cp_b1[o];
        #pragma unroll
        for (int c = 0; c < 32; c++) acc += cp_w1[o * 32 + c] * s_z[c][pos];
        s_z0[o][pos] = relu(acc);
    }
    // common path: z = 0 -> z0c = relu(cp_b1), pos-invariant
    if (t < 20) {
        float acc = cp_b2[t];
        #pragma unroll
        for (int c = 0; c < 20; c++) acc += cp_w2[t * 20 + c] * relu(cp_b1[c]);
        s_z1c[t] = relu(acc);
    }
    __syncthreads();
    for (int idx = t; idx < 20 * 56; idx += 256) {
        const int o = idx / 56, pos = idx % 56;
        float acc = cp_b2[o];
        #pragma unroll
        for (int c = 0; c < 20; c++) acc += cp_w2[o * 20 + c] * s_z0[c][pos];
        s_z1[o][pos] = relu(acc);
    }
    __syncthreads();

    // ---- 7. r = z1 * y ; cc conv chain, both paths ----
    for (int idx = t; idx < 2 * 8 * 56; idx += 256) {
        const int path = idx / (8 * 56);
        const int rem = idx % (8 * 56);
        const int o = rem / 56, pos = rem % 56;
        float acc = cc_b1[o];
        #pragma unroll
        for (int c = 0; c < 20; c++) {
            const float rv = (path ? s_z1c[c] : s_z1[c][pos]) * s_y2[c][pos];
            acc += cc_w1[o * 20 + c] * rv;
        }
        s_rc1[path][o][pos] = relu(acc);
    }
    __syncthreads();
    if (t < 2 * 56) {
        const int path = t / 56, pos = t % 56;
        float acc = cc_b2[0];
        #pragma unroll
        for (int c = 0; c < 8; c++) acc += cc_w2[c] * s_rc1[path][c][pos];
        s_rc2[path][pos] = relu(acc);
    }
    __syncthreads();
    if (t < 16) {
        const int path = t >> 3, w = t & 7;
        float acc = 0.0f;
        #pragma unroll
        for (int h = 0; h < 7; h++) acc += s_rc2[path][h * 8 + w];
        s_rsum[path][w] = acc;
    }
    __syncthreads();

    // ---- 8. Q network, both paths ----
    if (t < 32) {
        const int path = t >> 4, k = t & 15;
        float acc = q_b1[k];
        #pragma unroll
        for (int w = 0; w < 8; w++) acc += s_rsum[path][w] * q_w1[k * 8 + w];
        s_h1[path][k] = relu(acc);
    }
    __syncthreads();
    if (t < 32) {
        const int path = t >> 4, k = t & 15;
        float acc = q_b2[k];
        #pragma unroll
        for (int j = 0; j < 16; j++) acc += s_h1[path][j] * q_w2[k * 16 + j];
        s_h2[path][k] = relu(acc);
    }
    __syncthreads();
    if (t < 16) {
        const int path = t >> 3, o = t & 7;
        float acc = q_b3[o];
        #pragma unroll
        for (int j = 0; j < 16; j++) acc += s_h2[path][j] * q_w3[o * 16 + j];
        // g_q[0..7] = last-row q (path 0), g_q[8..15] = common q (path 1)
        g_q[path * 8 + o] = relu(acc);
    }
}

// Fill (B,8) fp32 output: last row gets g_q[0..7], all others g_q[8..15].
__global__ void __launch_bounds__(256)
frap_fill_kernel(float4* __restrict__ out, int n4)
{
    const int i = blockIdx.x * blockDim.x + threadIdx.x;
    if (i >= n4) return;
    // row = i/2, half = i&1. Last row occupies float4 slots n4-2, n4-1.
    const float4* src = (i >= n4 - 2)
        ? reinterpret_cast<const float4*>(&g_q[0])
        : reinterpret_cast<const float4*>(&g_q[8]);
    out[i] = src[i & 1];
}

extern "C" void kernel_launch(void* const* d_in, const int* in_sizes, int n_in,
                              void* d_out, int out_size) {
    const float* state = (const float*)d_in[0];
    const int B = in_sizes[0] / 16;

    const float* dv_w1 = (const float*)d_in[1];
    const float* dv_b1 = (const float*)d_in[2];
    const float* dv_w2 = (const float*)d_in[3];
    const float* dv_b2 = (const float*)d_in[4];
    const float* dp_w1 = (const float*)d_in[5];
    const float* dp_b1 = (const float*)d_in[6];
    const float* dp_w2 = (const float*)d_in[7];
    const float* dp_b2 = (const float*)d_in[8];
    const float* emb_w = (const float*)d_in[9];
    const float* emb_b = (const float*)d_in[10];
    const float* cp_w1 = (const float*)d_in[11];
    const float* cp_b1 = (const float*)d_in[12];
    const float* cp_w2 = (const float*)d_in[13];
    const float* cp_b2 = (const float*)d_in[14];
    const float* cm_w1 = (const float*)d_in[15];
    const float* cm_b1 = (const float*)d_in[16];
    const float* cm_w2 = (const float*)d_in[17];
    const float* cm_b2 = (const float*)d_in[18];
    const float* cm_w3 = (const float*)d_in[19];
    const float* cm_b3 = (const float*)d_in[20];
    const float* cc_w1 = (const float*)d_in[21];
    const float* cc_b1 = (const float*)d_in[22];
    const float* cc_w2 = (const float*)d_in[23];
    const float* cc_b2 = (const float*)d_in[24];
    const float* q_w1  = (const float*)d_in[25];
    const float* q_b1  = (const float*)d_in[26];
    const float* q_w2  = (const float*)d_in[27];
    const float* q_b2  = (const float*)d_in[28];
    const float* q_w3  = (const float*)d_in[29];
    const float* q_b3  = (const float*)d_in[30];
    const float* mask  = (const float*)d_in[31];

    frap_compute_kernel<<<1, 256>>>(
        state, B,
        dv_w1, dv_b1, dv_w2, dv_b2,
        dp_w1, dp_b1, dp_w2, dp_b2,
        emb_w, emb_b,
        cp_w1, cp_b1, cp_w2, cp_b2,
        cm_w1, cm_b1, cm_w2, cm_b2, cm_w3, cm_b3,
        cc_w1, cc_b1, cc_w2, cc_b2,
        q_w1, q_b1, q_w2, q_b2, q_w3, q_b3,
        mask);

    const int n4 = out_size / 4;  // number of float4 elements (B*2)
    frap_fill_kernel<<<(n4 + 255) / 256, 256>>>((float4*)d_out, n4);
}

// round 2
// speedup vs baseline: 1.2584x; 1.2584x over previous
#include <cuda_runtime.h>

#define NT 256

__device__ __forceinline__ float relu(float x) { return fmaxf(x, 0.0f); }

__constant__ int c_P0[8] = {0, 0, 4, 1, 2, 2, 6, 3};
__constant__ int c_P1[8] = {4, 1, 5, 5, 6, 3, 7, 7};

// All weights cached in shared (one batched prefetch, single DRAM latency exposure).
struct SW {
    float dv_w1[16], dv_b1[16], dv_w2[64], dv_b2[32];
    float dp_w1[16], dp_b1[16], dp_w2[64], dp_b2[32];
    float emb_w[128], emb_b[16];
    float cp_w1[640], cp_b1[20], cp_w2[400], cp_b2[20];
    float cm_w1[4],  cm_b1[4],  cm_w2[80],  cm_b2[20], cm_w3[400], cm_b3[20];
    float cc_w1[160], cc_b1[8], cc_w2[8],  cc_b2[4];
    float q_w1[128], q_b1[16], q_w2[256], q_b2[16], q_w3[128], q_b3[8];
    float mask[56], st[16];
};

__device__ __forceinline__ void cpsh(float* dst, const float* src, int n, int t) {
    for (int i = t; i < n; i += NT) dst[i] = src[i];
}

__global__ void __launch_bounds__(NT, 1)
frap_fused_kernel(
    const float* __restrict__ state, int B,
    const float* __restrict__ dv_w1, const float* __restrict__ dv_b1,
    const float* __restrict__ dv_w2, const float* __restrict__ dv_b2,
    const float* __restrict__ dp_w1, const float* __restrict__ dp_b1,
    const float* __restrict__ dp_w2, const float* __restrict__ dp_b2,
    const float* __restrict__ emb_w, const float* __restrict__ emb_b,
    const float* __restrict__ cp_w1, const float* __restrict__ cp_b1,
    const float* __restrict__ cp_w2, const float* __restrict__ cp_b2,
    const float* __restrict__ cm_w1, const float* __restrict__ cm_b1,
    const float* __restrict__ cm_w2, const float* __restrict__ cm_b2,
    const float* __restrict__ cm_w3, const float* __restrict__ cm_b3,
    const float* __restrict__ cc_w1, const float* __restrict__ cc_b1,
    const float* __restrict__ cc_w2, const float* __restrict__ cc_b2,
    const float* __restrict__ q_w1,  const float* __restrict__ q_b1,
    const float* __restrict__ q_w2,  const float* __restrict__ q_b2,
    const float* __restrict__ q_w3,  const float* __restrict__ q_b3,
    const float* __restrict__ mask,
    float4* __restrict__ out, int n4)
{
    __shared__ SW w;
    __shared__ float s_cat[8][8];
    __shared__ float s_d[8][16];
    __shared__ float s_pd[8][16];
    __shared__ float s_z[32][56];
    __shared__ float s_y1[20][56];
    __shared__ float s_y2[20][56];
    __shared__ float s_z0[20][56];
    __shared__ float s_z1[20][56];
    __shared__ float s_z1c[20];
    __shared__ float s_rc1[2][8][56];
    __shared__ float s_rc2[2][56];
    __shared__ float s_rsum[2][8];
    __shared__ float s_h1[2][16];
    __shared__ float s_h2[2][16];
    __shared__ __align__(16) float s_q[2][8];  // [0]=last row, [1]=common

    const int t = threadIdx.x;

    // ---- 0. Batched weight prefetch (all loads independent; one latency exposure) ----
    cpsh(w.dv_w1, dv_w1, 16, t);  cpsh(w.dv_b1, dv_b1, 16, t);
    cpsh(w.dv_w2, dv_w2, 64, t);  cpsh(w.dv_b2, dv_b2, 32, t);
    cpsh(w.dp_w1, dp_w1, 16, t);  cpsh(w.dp_b1, dp_b1, 16, t);
    cpsh(w.dp_w2, dp_w2, 64, t);  cpsh(w.dp_b2, dp_b2, 32, t);
    cpsh(w.emb_w, emb_w, 128, t); cpsh(w.emb_b, emb_b, 16, t);
    cpsh(w.cp_w1, cp_w1, 640, t); cpsh(w.cp_b1, cp_b1, 20, t);
    cpsh(w.cp_w2, cp_w2, 400, t); cpsh(w.cp_b2, cp_b2, 20, t);
    cpsh(w.cm_w1, cm_w1, 4, t);   cpsh(w.cm_b1, cm_b1, 4, t);
    cpsh(w.cm_w2, cm_w2, 80, t);  cpsh(w.cm_b2, cm_b2, 20, t);
    cpsh(w.cm_w3, cm_w3, 400, t); cpsh(w.cm_b3, cm_b3, 20, t);
    cpsh(w.cc_w1, cc_w1, 160, t); cpsh(w.cc_b1, cc_b1, 8, t);
    cpsh(w.cc_w2, cc_w2, 8, t);   cpsh(w.cc_b2, cc_b2, 1, t);
    cpsh(w.q_w1, q_w1, 128, t);   cpsh(w.q_b1, q_b1, 16, t);
    cpsh(w.q_w2, q_w2, 256, t);   cpsh(w.q_b2, q_b2, 16, t);
    cpsh(w.q_w3, q_w3, 128, t);   cpsh(w.q_b3, q_b3, 8, t);
    cpsh(w.mask, mask, 56, t);
    cpsh(w.st, state + (size_t)(B - 1) * 16, 16, t);
    __syncthreads();

    // ---- 1. Per-phase demand MLPs on state[B-1] ----
    if (t < 8) {
        const int p = t;
        const float sv = w.st[p];       // s[:8] -> dv_*
        const float sp = w.st[8 + p];   // s[8:16] -> dp_*
        float h0 = relu(sv * w.dv_w1[p * 2 + 0] + w.dv_b1[p * 2 + 0]);
        float h1 = relu(sv * w.dv_w1[p * 2 + 1] + w.dv_b1[p * 2 + 1]);
        #pragma unroll
        for (int o = 0; o < 4; o++)
            s_cat[p][o] = relu(h0 * w.dv_w2[p * 8 + o * 2 + 0] +
                               h1 * w.dv_w2[p * 8 + o * 2 + 1] + w.dv_b2[p * 4 + o]);
        h0 = relu(sp * w.dp_w1[p * 2 + 0] + w.dp_b1[p * 2 + 0]);
        h1 = relu(sp * w.dp_w1[p * 2 + 1] + w.dp_b1[p * 2 + 1]);
        #pragma unroll
        for (int o = 0; o < 4; o++)
            s_cat[p][4 + o] = relu(h0 * w.dp_w2[p * 8 + o * 2 + 0] +
                                   h1 * w.dp_w2[p * 8 + o * 2 + 1] + w.dp_b2[p * 4 + o]);
    }
    // ---- 5a. Mask chain stage 1+2 fused (independent of stage 1; overlap) ----
    for (int idx = t; idx < 20 * 56; idx += NT) {
        const int o = idx / 56, pos = idx % 56;
        const float m = w.mask[pos];
        float acc = w.cm_b2[o];
        #pragma unroll
        for (int c = 0; c < 4; c++)
            acc += w.cm_w2[o * 4 + c] * relu(w.cm_w1[c] * m + w.cm_b1[c]);
        s_y1[o][pos] = relu(acc);
    }
    // common cp-chain (pos-invariant)
    if (t >= 32 && t < 52) {
        const int o = t - 32;
        float acc = w.cp_b2[o];
        #pragma unroll
        for (int c = 0; c < 20; c++) acc += w.cp_w2[o * 20 + c] * relu(w.cp_b1[c]);
        s_z1c[o] = relu(acc);
    }
    __syncthreads();

    // ---- 2. Embedding ----
    if (t < 128) {
        const int p = t >> 4, k = t & 15;
        float acc = w.emb_b[k];
        #pragma unroll
        for (int j = 0; j < 8; j++) acc += s_cat[p][j] * w.emb_w[k * 8 + j];
        s_d[p][k] = relu(acc);
    }
    // ---- 5b. Mask chain stage 3 (independent) on threads 128..255 + all later ----
    __syncthreads();

    // ---- 3. Phase-pair demand ----
    if (t < 128) {
        const int q = t >> 4, k = t & 15;
        s_pd[q][k] = s_d[c_P0[q]][k] + s_d[c_P1[q]][k];
    }
    // 5b (y2) in parallel with step 3 using all threads next pass
    for (int idx = t; idx < 20 * 56; idx += NT) {
        const int o = idx / 56, pos = idx % 56;
        float acc = w.cm_b3[o];
        #pragma unroll
        for (int c = 0; c < 20; c++) acc += w.cm_w3[o * 20 + c] * s_y1[c][pos];
        s_y2[o][pos] = relu(acc);
    }
    __syncthreads();

    // ---- 4. Build z ((7,8,32) scatter viewed as (32,7,8)) ----
    for (int idx = t; idx < 1792; idx += NT) {
        const int c = idx / 56, pos = idx % 56;
        const int r = idx >> 8, col = (idx >> 5) & 7, k = idx & 31;
        const int j = col;
        const int i = (r < j) ? r : r + 1;
        s_z[c][pos] = (k < 16) ? s_pd[i][k] : s_pd[j][k - 16];
    }
    __syncthreads();

    // ---- 6. cp conv chain (last path) ----
    for (int idx = t; idx < 20 * 56; idx += NT) {
        const int o = idx / 56, pos = idx % 56;
        float acc = w.cp_b1[o];
        #pragma unroll
        for (int c = 0; c < 32; c++) acc += w.cp_w1[o * 32 + c] * s_z[c][pos];
        s_z0[o][pos] = relu(acc);
    }
    __syncthreads();
    for (int idx = t; idx < 20 * 56; idx += NT) {
        const int o = idx / 56, pos = idx % 56;
        float acc = w.cp_b2[o];
        #pragma unroll
        for (int c = 0; c < 20; c++) acc += w.cp_w2[o * 20 + c] * s_z0[c][pos];
        s_z1[o][pos] = relu(acc);
    }
    __syncthreads();

    // ---- 7. r = z1 * y ; cc conv chain, both paths ----
    for (int idx = t; idx < 2 * 8 * 56; idx += NT) {
        const int path = idx / (8 * 56);
        const int rem = idx % (8 * 56);
        const int o = rem / 56, pos = rem % 56;
        float acc = w.cc_b1[o];
        #pragma unroll
        for (int c = 0; c < 20; c++) {
            const float rv = (path ? s_z1c[c] : s_z1[c][pos]) * s_y2[c][pos];
            acc += w.cc_w1[o * 20 + c] * rv;
        }
        s_rc1[path][o][pos] = relu(acc);
    }
    __syncthreads();
    if (t < 2 * 56) {
        const int path = t / 56, pos = t % 56;
        float acc = w.cc_b2[0];
        #pragma unroll
        for (int c = 0; c < 8; c++) acc += w.cc_w2[c] * s_rc1[path][c][pos];
        s_rc2[path][pos] = relu(acc);
    }
    __syncthreads();
    if (t < 16) {
        const int path = t >> 3, ww = t & 7;
        float acc = 0.0f;
        #pragma unroll
        for (int h = 0; h < 7; h++) acc += s_rc2[path][h * 8 + ww];
        s_rsum[path][ww] = acc;
    }
    __syncthreads();

    // ---- 8. Q network, both paths ----
    if (t < 32) {
        const int path = t >> 4, k = t & 15;
        float acc = w.q_b1[k];
        #pragma unroll
        for (int j = 0; j < 8; j++) acc += s_rsum[path][j] * w.q_w1[k * 8 + j];
        s_h1[path][k] = relu(acc);
    }
    __syncthreads();
    if (t < 32) {
        const int path = t >> 4, k = t & 15;
        float acc = w.q_b2[k];
        #pragma unroll
        for (int j = 0; j < 16; j++) acc += s_h1[path][j] * w.q_w2[k * 16 + j];
        s_h2[path][k] = relu(acc);
    }
    __syncthreads();
    if (t < 16) {
        const int path = t >> 3, o = t & 7;
        float acc = w.q_b3[o];
        #pragma unroll
        for (int j = 0; j < 16; j++) acc += s_h2[path][j] * w.q_w3[o * 16 + j];
        s_q[path][o] = relu(acc);
    }
    __syncthreads();

    // ---- 9. Fill output: rows 0..B-2 get common q, row B-1 gets last q ----
    const float4 qc0 = *reinterpret_cast<const float4*>(&s_q[1][0]);
    const float4 qc1 = *reinterpret_cast<const float4*>(&s_q[1][4]);
    const int stride = gridDim.x * NT;
    for (int i = blockIdx.x * NT + t; i < n4 - 2; i += stride)
        out[i] = (i & 1) ? qc1 : qc0;
    if (blockIdx.x == 0 && t < 2) {
        out[n4 - 2 + t] = (t == 0)
            ? *reinterpret_cast<const float4*>(&s_q[0][0])
            : *reinterpret_cast<const float4*>(&s_q[0][4]);
    }
}

extern "C" void kernel_launch(void* const* d_in, const int* in_sizes, int n_in,
                              void* d_out, int out_size) {
    const float* state = (const float*)d_in[0];
    const int B = in_sizes[0] / 16;

    const float* dv_w1 = (const float*)d_in[1];
    const float* dv_b1 = (const float*)d_in[2];
    const float* dv_w2 = (const float*)d_in[3];
    const float* dv_b2 = (const float*)d_in[4];
    const float* dp_w1 = (const float*)d_in[5];
    const float* dp_b1 = (const float*)d_in[6];
    const float* dp_w2 = (const float*)d_in[7];
    const float* dp_b2 = (const float*)d_in[8];
    const float* emb_w = (const float*)d_in[9];
    const float* emb_b = (const float*)d_in[10];
    const float* cp_w1 = (const float*)d_in[11];
    const float* cp_b1 = (const float*)d_in[12];
    const float* cp_w2 = (const float*)d_in[13];
    const float* cp_b2 = (const float*)d_in[14];
    const float* cm_w1 = (const float*)d_in[15];
    const float* cm_b1 = (const float*)d_in[16];
    const float* cm_w2 = (const float*)d_in[17];
    const float* cm_b2 = (const float*)d_in[18];
    const float* cm_w3 = (const float*)d_in[19];
    const float* cm_b3 = (const float*)d_in[20];
    const float* cc_w1 = (const float*)d_in[21];
    const float* cc_b1 = (const float*)d_in[22];
    const float* cc_w2 = (const float*)d_in[23];
    const float* cc_b2 = (const float*)d_in[24];
    const float* q_w1  = (const float*)d_in[25];
    const float* q_b1  = (const float*)d_in[26];
    const float* q_w2  = (const float*)d_in[27];
    const float* q_b2  = (const float*)d_in[28];
    const float* q_w3  = (const float*)d_in[29];
    const float* q_b3  = (const float*)d_in[30];
    const float* mask  = (const float*)d_in[31];

    const int n4 = out_size / 4;
    frap_fused_kernel<<<148, NT>>>(
        state, B,
        dv_w1, dv_b1, dv_w2, dv_b2,
        dp_w1, dp_b1, dp_w2, dp_b2,
        emb_w, emb_b,
        cp_w1, cp_b1, cp_w2, cp_b2,
        cm_w1, cm_b1, cm_w2, cm_b2, cm_w3, cm_b3,
        cc_w1, cc_b1, cc_w2, cc_b2,
        q_w1, q_b1, q_w2, q_b2, q_w3, q_b3,
        mask,
        (float4*)d_out, n4);
}